// round 16
// baseline (speedup 1.0000x reference)
#include <cuda_runtime.h>
#include <cuda_fp16.h>
#include <cstddef>

#define NN   50000
#define NE   800000
#define FIN  512
#define FHID 128
#define FOUT 64
#define NTILES   ((NN + 127) / 128)                 // 391
#define GRID1    148                                // 1 persistent block / SM
#define CSRB     98                                 // csr blocks (co-resident)
#define CSRT     512                                // csr threads/block

// ---------------- scratch (device globals) ---------------------------------
// g_outdeg/g_indeg invariant: zero at entry of every kernel_launch (zero at
// module load; agg2 re-zeroes them at the end of every launch).
__device__ __align__(16) int    g_outdeg[NN];
__device__ __align__(16) int    g_indeg[NN];
__device__ __align__(16) float  g_onorm[NN];
__device__ __align__(16) float  g_inorm[NN];
__device__ __align__(16) int    g_rowptr[NN + 1];
__device__ __align__(16) int    g_cursor[NN];
__device__ __align__(16) int    g_srcs[NE];              // edge srcs sorted by dst
__device__ __align__(16) unsigned long long g_state[CSRB]; // lookback: (val<<2)|flag
__device__ int g_bar1, g_bar2;                           // grid barriers (csr)
__device__ __align__(16) float  g_W1p[FIN * FHID];       // W1 tf32, MMA-fragment-permuted
__device__ __align__(16) float  g_W2p[FHID * FOUT];      // W2 tf32, MMA-fragment-permuted
__device__ __align__(16) __half g_h1[(size_t)NN * FHID]; // x @ W1 (NO norm), fp16
__device__ __align__(16) __half g_h2[(size_t)NN * FOUT]; // x2 @ W2, fp16

#define CP_COMMIT() asm volatile("cp.async.commit_group;\n" ::: "memory")
#define CP_WAIT(n)  asm volatile("cp.async.wait_group %0;\n" :: "n"(n) : "memory")

__device__ __forceinline__ void cp_async16(void* smem, const void* g, bool pred) {
    unsigned saddr = (unsigned)__cvta_generic_to_shared(smem);
    int sz = pred ? 16 : 0;   // src-size 0 -> zero-fill, no read
    asm volatile("cp.async.cg.shared.global [%0], [%1], 16, %2;\n"
                 :: "r"(saddr), "l"(g), "r"(sz));
}

__device__ __forceinline__ unsigned f2tf32(float x) {
    unsigned r;
    asm("cvt.rna.tf32.f32 %0, %1;" : "=r"(r) : "f"(x));
    return r;
}

__device__ __forceinline__ void mma_tf32(float* c, const unsigned* a, const unsigned* b) {
    asm volatile(
        "mma.sync.aligned.m16n8k8.row.col.f32.tf32.tf32.f32 "
        "{%0,%1,%2,%3}, {%4,%5,%6,%7}, {%8,%9}, {%0,%1,%2,%3};"
        : "+f"(c[0]), "+f"(c[1]), "+f"(c[2]), "+f"(c[3])
        : "r"(a[0]), "r"(a[1]), "r"(a[2]), "r"(a[3]), "r"(b[0]), "r"(b[1]));
}

// accumulate 8 halves (uint4) scaled by s into a[0..7]
__device__ __forceinline__ void acc8(float* a, uint4 u, float s) {
    float2 f;
    f = __half22float2(*(__half2*)&u.x); a[0] = fmaf(f.x, s, a[0]); a[1] = fmaf(f.y, s, a[1]);
    f = __half22float2(*(__half2*)&u.y); a[2] = fmaf(f.x, s, a[2]); a[3] = fmaf(f.y, s, a[3]);
    f = __half22float2(*(__half2*)&u.z); a[4] = fmaf(f.x, s, a[4]); a[5] = fmaf(f.y, s, a[5]);
    f = __half22float2(*(__half2*)&u.w); a[6] = fmaf(f.x, s, a[6]); a[7] = fmaf(f.y, s, a[7]);
}

// ---------------- weight prep + csr-state reset ------------------------------
__global__ void cvtW_kernel(const float* __restrict__ W1, const float* __restrict__ W2) {
    int i = blockIdx.x * blockDim.x + threadIdx.x;
    if (i < FIN * FHID) {
        int p = i >> 1, f = i & 1;
        int l = p & 31, cb = (p >> 5) & 15, ks = (p >> 9) & 3, it = p >> 11;
        int srow = it * 32 + ks * 8 + f * 4 + (l & 3);
        int scol = cb * 8 + (l >> 2);
        g_W1p[i] = __uint_as_float(f2tf32(W1[srow * FHID + scol]));
    } else if (i < FIN * FHID + FHID * FOUT) {
        int j = i - FIN * FHID;
        int p = j >> 1, f = j & 1;
        int l = p & 31, cb = (p >> 5) & 7, ksg = p >> 8;
        int srow = ksg * 8 + f * 4 + (l & 3);
        int scol = cb * 8 + (l >> 2);
        g_W2p[j] = __uint_as_float(f2tf32(W2[srow * FOUT + scol]));
    }
    // reset csr lookback/barrier state (stream-ordered before csr_kernel)
    if (i < CSRB) g_state[i] = 0ULL;
    if (i == CSRB)     g_bar1 = 0;
    if (i == CSRB + 1) g_bar2 = 0;
}

// ---------------- CSR build: hist + lookback-scan + place, ONE kernel -------
// 98 blocks x 512 threads: grid < #SMs -> all blocks co-resident, so plain
// atomic spin barriers are deadlock-free.
__device__ __forceinline__ void grid_barrier(int* ctr, int tid) {
    __threadfence();
    __syncthreads();
    if (tid == 0) {
        atomicAdd(ctr, 1);
        while (atomicAdd(ctr, 0) < CSRB) {}
    }
    __syncthreads();
    __threadfence();
}

__global__ __launch_bounds__(CSRT) void csr_kernel(const int* __restrict__ src,
                                                   const int* __restrict__ dst) {
    __shared__ int sh[CSRT];
    __shared__ int sh_prefix;
    const int t = threadIdx.x;
    const int c = blockIdx.x;
    const int gsz = CSRB * CSRT;   // 50176
    const int g = c * CSRT + t;

    // --- phase A: degree histogram (grid-stride, independent iters for ILP)
#pragma unroll 4
    for (int i = g; i < NE; i += gsz) {
        atomicAdd(&g_outdeg[src[i]], 1);
        atomicAdd(&g_indeg[dst[i]], 1);
    }
    grid_barrier(&g_bar1, t);

    // --- phase B: decoupled-lookback exclusive scan of indeg -> rowptr/cursor
    int v = (g < NN) ? g_indeg[g] : 0;
    sh[t] = v;
    __syncthreads();
    for (int off = 1; off < CSRT; off <<= 1) {
        int a = (t >= off) ? sh[t - off] : 0;
        __syncthreads();
        sh[t] += a;
        __syncthreads();
    }
    if (t == 0) {
        int T = sh[CSRT - 1];
        atomicExch(&g_state[c], ((unsigned long long)(unsigned)T << 2) | 1ULL);
        long long prefix = 0;
        for (int p = c - 1; p >= 0; ) {
            unsigned long long w;
            do { w = atomicAdd(&g_state[p], 0ULL); } while ((w & 3ULL) == 0ULL);
            prefix += (long long)(w >> 2);
            if ((w & 3ULL) == 2ULL) break;
            p--;
        }
        atomicExch(&g_state[c],
                   ((unsigned long long)(prefix + T) << 2) | 2ULL);
        sh_prefix = (int)prefix;
    }
    __syncthreads();
    if (g < NN) {
        int p0 = sh_prefix + sh[t] - v;   // exclusive prefix
        g_rowptr[g] = p0;
        g_cursor[g] = p0;
        g_onorm[g] = rsqrtf(fmaxf((float)g_outdeg[g], 1.0f));
        g_inorm[g] = rsqrtf(fmaxf((float)v, 1.0f));
        if (g == NN - 1) g_rowptr[NN] = NE;
    }
    grid_barrier(&g_bar2, t);

    // --- phase C: place edges into dst-sorted order
#pragma unroll 4
    for (int i = g; i < NE; i += gsz) {
        int p = atomicAdd(&g_cursor[dst[i]], 1);
        g_srcs[p] = src[i];
    }
}

// ---------------- GEMM1: persistent, tf32 MMA, 3-stage cp.async -------------
// R12 configuration verbatim (best measured: 51.1us). BM=128, BN=128, BK=32,
// grid=148 (1 block/SM), 256 threads, 8 warps (4x2), warp tile 32x64.
#define AS_STRIDE 36   // words; A-frag reads hit 32 distinct banks, 16B rows
#define BSTAGE    (32 * 128)   // 4096 words, dense permuted
__global__ __launch_bounds__(256, 1) void gemm1_kernel(const float* __restrict__ A) {
    __shared__ float As[3][128 * AS_STRIDE];
    __shared__ float Bs[3][BSTAGE];
    const int tid  = threadIdx.x;
    const int wid  = tid >> 5;
    const int lane = tid & 31;
    const int warp_m = wid >> 1;
    const int warp_n = wid & 1;
    const int lq = lane >> 2;
    const int lr = lane & 3;

    const int my_nt = (NTILES - 1 - blockIdx.x) / GRID1 + 1;
    const int J = my_nt * 16;   // flat (tile, k-iter) iterations

    float acc[2][8][4];

    auto load_stage = [&](int buf, int j) {
        const int row0 = (blockIdx.x + (j >> 4) * GRID1) * 128;
        const int k0 = (j & 15) * 32;
#pragma unroll
        for (int l = tid; l < 128 * 8; l += 256) {      // A: 128x32
            int r = l >> 3, c4 = l & 7;
            int grow = row0 + r;
            bool ok = grow < NN;
            const float* gp = A + (size_t)(ok ? grow : 0) * FIN + k0 + (c4 << 2);
            cp_async16(&As[buf][r * AS_STRIDE + (c4 << 2)], gp, ok);
        }
        const float* bg = g_W1p + (size_t)(j & 15) * BSTAGE;
#pragma unroll
        for (int l = tid; l < BSTAGE / 4; l += 256) {   // B: dense 16KB
            cp_async16(&Bs[buf][l << 2], bg + (l << 2), true);
        }
    };

    load_stage(0, 0); CP_COMMIT();
    load_stage(1, 1); CP_COMMIT();

    for (int j = 0; j < J; ++j) {
        if (j + 1 < J) CP_WAIT(1); else CP_WAIT(0);
        __syncthreads();   // stage j visible; all warps done with stage j-1
        if ((j & 15) == 0) {
#pragma unroll
            for (int mt = 0; mt < 2; mt++)
#pragma unroll
                for (int nt = 0; nt < 8; nt++)
#pragma unroll
                    for (int q = 0; q < 4; q++) acc[mt][nt][q] = 0.f;
        }
        const int buf = j % 3;
        const float* as = As[buf];
        const float* bs = Bs[buf];
#pragma unroll
        for (int ks = 0; ks < 4; ks++) {
            const int kk = ks << 3;
            unsigned af[2][4];
#pragma unroll
            for (int mt = 0; mt < 2; mt++) {
                int row = warp_m * 32 + mt * 16 + lq;
                af[mt][0] = f2tf32(as[row * AS_STRIDE + kk + lr]);
                af[mt][1] = f2tf32(as[(row + 8) * AS_STRIDE + kk + lr]);
                af[mt][2] = f2tf32(as[row * AS_STRIDE + kk + 4 + lr]);
                af[mt][3] = f2tf32(as[(row + 8) * AS_STRIDE + kk + 4 + lr]);
            }
            unsigned bf[8][2];
#pragma unroll
            for (int nt = 0; nt < 8; nt++) {
                int cb = warp_n * 8 + nt;
                const float2 bp = *(const float2*)&bs[((ks * 16 + cb) * 32 + lane) * 2];
                bf[nt][0] = __float_as_uint(bp.x);
                bf[nt][1] = __float_as_uint(bp.y);
            }
#pragma unroll
            for (int mt = 0; mt < 2; mt++)
#pragma unroll
                for (int nt = 0; nt < 8; nt++)
                    mma_tf32(acc[mt][nt], af[mt], bf[nt]);
        }
        if (j + 2 < J) {   // prefetch distance 2; buffer consumed at j-1
            load_stage((j + 2) % 3, j + 2);
            CP_COMMIT();
        }
        if ((j & 15) == 15) {   // tile epilogue: regs -> gmem
            const int row0 = (blockIdx.x + (j >> 4) * GRID1) * 128;
#pragma unroll
            for (int mt = 0; mt < 2; mt++) {
                int rowA = row0 + warp_m * 32 + mt * 16 + lq;
                int rowB = rowA + 8;
#pragma unroll
                for (int nt = 0; nt < 8; nt++) {
                    int col = warp_n * 64 + nt * 8 + (lr << 1);
                    if (rowA < NN)
                        *(__half2*)(g_h1 + (size_t)rowA * FHID + col) =
                            __float22half2_rn(make_float2(acc[mt][nt][0], acc[mt][nt][1]));
                    if (rowB < NN)
                        *(__half2*)(g_h1 + (size_t)rowB * FHID + col) =
                            __float22half2_rn(make_float2(acc[mt][nt][2], acc[mt][nt][3]));
                }
            }
        }
    }
}

// ---------------- layer2: fused agg1 + epilogue1 + GEMM2 (tf32 MMA) --------
// BM=64 rows/block. Gather: 16 half-warps work-steal rows from a smem queue.
// Then h2 = x2 @ W2 on tensor cores -> fp16.  (UNCHANGED: profiled this round)
__global__ __launch_bounds__(256) void layer2_kernel(const float* __restrict__ b1) {
    __shared__ float Ws[FHID * FOUT];   // 8192 words, dense permuted W2p
    __shared__ float x2s[64][132];
    __shared__ int nextrow;
    const int tid  = threadIdx.x;
    const int wid  = tid >> 5;
    const int lane = tid & 31;
    const int r0 = blockIdx.x * 64;

    if (tid == 0) nextrow = 16;
#pragma unroll
    for (int l = tid; l < FHID * FOUT / 4; l += 256)
        *(float4*)&Ws[l << 2] = *(const float4*)&g_W2p[l << 2];
    __syncthreads();   // nextrow + Ws visible

    // Gather + epilogue1: half-warp h starts on row h, then steals rows 16..63.
    {
        const int sub = lane >> 4;     // 0,1
        const int q   = lane & 15;     // 0..15 -> halves [q*8, q*8+8)
        const unsigned hmask = 0xFFFFu << (sub * 16);
        float4 bb0 = *(const float4*)(b1 + q * 8);
        float4 bb1 = *(const float4*)(b1 + q * 8 + 4);
        int row = wid * 2 + sub;       // static first row: 0..15
        while (row < 64) {
            int grow = r0 + row;
            float4 o0 = make_float4(0.f, 0.f, 0.f, 0.f);
            float4 o1 = make_float4(0.f, 0.f, 0.f, 0.f);
            if (grow < NN) {
                float a[8] = {0.f, 0.f, 0.f, 0.f, 0.f, 0.f, 0.f, 0.f};
                int beg = g_rowptr[grow], end = g_rowptr[grow + 1];
                int e = beg;
                for (; e + 1 < end; e += 2) {
                    int s0 = g_srcs[e], s1 = g_srcs[e + 1];
                    uint4 u0 = *(const uint4*)(g_h1 + (size_t)s0 * FHID + q * 8);
                    uint4 u1 = *(const uint4*)(g_h1 + (size_t)s1 * FHID + q * 8);
                    float os0 = g_onorm[s0], os1 = g_onorm[s1];
                    acc8(a, u0, os0);
                    acc8(a, u1, os1);
                }
                if (e < end) {
                    int s0 = g_srcs[e];
                    uint4 u0 = *(const uint4*)(g_h1 + (size_t)s0 * FHID + q * 8);
                    acc8(a, u0, g_onorm[s0]);
                }
                float inn = g_inorm[grow], onn = g_onorm[grow];
                o0.x = fmaxf(fmaf(a[0], inn, bb0.x), 0.f) * onn;
                o0.y = fmaxf(fmaf(a[1], inn, bb0.y), 0.f) * onn;
                o0.z = fmaxf(fmaf(a[2], inn, bb0.z), 0.f) * onn;
                o0.w = fmaxf(fmaf(a[3], inn, bb0.w), 0.f) * onn;
                o1.x = fmaxf(fmaf(a[4], inn, bb1.x), 0.f) * onn;
                o1.y = fmaxf(fmaf(a[5], inn, bb1.y), 0.f) * onn;
                o1.z = fmaxf(fmaf(a[6], inn, bb1.z), 0.f) * onn;
                o1.w = fmaxf(fmaf(a[7], inn, bb1.w), 0.f) * onn;
            }
            *(float4*)&x2s[row][q * 8]     = o0;
            *(float4*)&x2s[row][q * 8 + 4] = o1;
            // steal next row
            int nr = 0;
            if (q == 0) nr = atomicAdd(&nextrow, 1);
            nr = __shfl_sync(hmask, nr, sub * 16);
            row = nr;
        }
    }
    __syncthreads();

    // MMA phase: warp_m = wid>>1 (0..3) x 16 rows; warp_n = wid&1 (0..1) x 32 cols.
    const int lq = lane >> 2;
    const int lr = lane & 3;
    const int warp_m = wid >> 1;
    const int warp_n = wid & 1;
    float acc[4][4];
#pragma unroll
    for (int nt = 0; nt < 4; nt++)
#pragma unroll
        for (int qq = 0; qq < 4; qq++) acc[nt][qq] = 0.f;
    const int arow = warp_m * 16 + lq;
#pragma unroll
    for (int ks = 0; ks < 16; ks++) {
        const int kk = ks << 3;
        unsigned af[4];
        af[0] = f2tf32(x2s[arow][kk + lr]);
        af[1] = f2tf32(x2s[arow + 8][kk + lr]);
        af[2] = f2tf32(x2s[arow][kk + 4 + lr]);
        af[3] = f2tf32(x2s[arow + 8][kk + 4 + lr]);
        unsigned bf[4][2];
#pragma unroll
        for (int nt = 0; nt < 4; nt++) {
            int cb = warp_n * 4 + nt;
            const float2 bp = *(const float2*)&Ws[((ks * 8 + cb) * 32 + lane) * 2];
            bf[nt][0] = __float_as_uint(bp.x);
            bf[nt][1] = __float_as_uint(bp.y);
        }
#pragma unroll
        for (int nt = 0; nt < 4; nt++)
            mma_tf32(acc[nt], af, bf[nt]);
    }
    int rowA = r0 + warp_m * 16 + lq;
    int rowB = rowA + 8;
#pragma unroll
    for (int nt = 0; nt < 4; nt++) {
        int col = warp_n * 32 + nt * 8 + (lr << 1);
        if (rowA < NN)
            *(__half2*)(g_h2 + (size_t)rowA * FOUT + col) =
                __float22half2_rn(make_float2(acc[nt][0], acc[nt][1]));
        if (rowB < NN)
            *(__half2*)(g_h2 + (size_t)rowB * FOUT + col) =
                __float22half2_rn(make_float2(acc[nt][2], acc[nt][3]));
    }
}

// ---------------- agg2: 4 dst per warp; re-zeroes degree arrays ------------
// out = segsum(h2[src]) * inorm + b2.  No block barrier -> static schedule OK.
__global__ void agg2_kernel(const float* __restrict__ b2, float* __restrict__ out) {
    {
        int z = blockIdx.x * 32 + threadIdx.x;
        if (threadIdx.x < 32 && z < NN) { g_outdeg[z] = 0; g_indeg[z] = 0; }
    }
    int gw = (int)(((long long)blockIdx.x * blockDim.x + threadIdx.x) >> 5);
    int lane = threadIdx.x & 31;
    int sub = lane >> 3;           // 0..3
    int q = lane & 7;              // halves [q*8, q*8+8)
    int d = gw * 4 + sub;
    if (d >= NN) return;
    int beg = g_rowptr[d], end = g_rowptr[d + 1];
    float a[8] = {0.f, 0.f, 0.f, 0.f, 0.f, 0.f, 0.f, 0.f};
    int e = beg;
    for (; e + 1 < end; e += 2) {
        int s0 = g_srcs[e], s1 = g_srcs[e + 1];
        uint4 u0 = *(const uint4*)(g_h2 + (size_t)s0 * FOUT + q * 8);
        uint4 u1 = *(const uint4*)(g_h2 + (size_t)s1 * FOUT + q * 8);
        acc8(a, u0, 1.0f);
        acc8(a, u1, 1.0f);
    }
    if (e < end) {
        int s0 = g_srcs[e];
        uint4 u0 = *(const uint4*)(g_h2 + (size_t)s0 * FOUT + q * 8);
        acc8(a, u0, 1.0f);
    }
    float inn = g_inorm[d];
    float4 bb0 = *(const float4*)(b2 + q * 8);
    float4 bb1 = *(const float4*)(b2 + q * 8 + 4);
    float4 r0, r1;
    r0.x = fmaf(a[0], inn, bb0.x); r0.y = fmaf(a[1], inn, bb0.y);
    r0.z = fmaf(a[2], inn, bb0.z); r0.w = fmaf(a[3], inn, bb0.w);
    r1.x = fmaf(a[4], inn, bb1.x); r1.y = fmaf(a[5], inn, bb1.y);
    r1.z = fmaf(a[6], inn, bb1.z); r1.w = fmaf(a[7], inn, bb1.w);
    *(float4*)(out + (size_t)d * FOUT + q * 8)     = r0;
    *(float4*)(out + (size_t)d * FOUT + q * 8 + 4) = r1;
}

// ---------------- launch: layer2 is now kernel submission #4 ----------------
// cvtW(#1,main) -> gemm1(#2,main); csr(#3,s1, waits cvtW via event);
// layer2(#4,main, waits csr) <- PROFILED; agg2(#5,main).
extern "C" void kernel_launch(void* const* d_in, const int* in_sizes, int n_in,
                              void* d_out, int out_size) {
    const float* features = (const float*)d_in[0];
    const int*   esrc     = (const int*)d_in[1];
    const int*   edst     = (const int*)d_in[2];
    const float* W1       = (const float*)d_in[3];
    const float* b1       = (const float*)d_in[4];
    const float* W2       = (const float*)d_in[5];
    const float* b2       = (const float*)d_in[6];
    float* out = (float*)d_out;

    static cudaStream_t s1 = nullptr;
    static cudaEvent_t evW = nullptr, evJoin = nullptr;
    if (s1 == nullptr) {
        cudaStreamCreateWithFlags(&s1, cudaStreamNonBlocking);
        cudaEventCreateWithFlags(&evW, cudaEventDisableTiming);
        cudaEventCreateWithFlags(&evJoin, cudaEventDisableTiming);
    }

    cvtW_kernel<<<(FIN * FHID + FHID * FOUT + 255) / 256, 256>>>(W1, W2);  // #1
    cudaEventRecord(evW, 0);
    gemm1_kernel<<<GRID1, 256>>>(features);                                // #2
    cudaStreamWaitEvent(s1, evW, 0);
    csr_kernel<<<CSRB, CSRT, 0, s1>>>(esrc, edst);                         // #3 (s1)
    cudaEventRecord(evJoin, s1);
    cudaStreamWaitEvent(0, evJoin, 0);
    layer2_kernel<<<(NN + 63) / 64, 256>>>(b1);                            // #4 <- profiled
    agg2_kernel<<<(NN + 31) / 32, 256>>>(b2, out);                         // #5
}

// round 17
// speedup vs baseline: 1.0930x; 1.0930x over previous
#include <cuda_runtime.h>
#include <cuda_fp16.h>
#include <cstddef>

#define NN   50000
#define NE   800000
#define FIN  512
#define FHID 128
#define FOUT 64
#define SCAN_BLK 512
#define SCAN_NB  ((NN + SCAN_BLK - 1) / SCAN_BLK)   // 98
#define NTILES   ((NN + 127) / 128)                 // 391
#define GRID1    148                                // 1 persistent block / SM

// ---------------- scratch (device globals) ---------------------------------
// g_outdeg/g_indeg invariant: zero at entry of every kernel_launch (zero at
// module load; agg2 re-zeroes them at the end of every launch).
__device__ __align__(16) int    g_outdeg[NN];
__device__ __align__(16) int    g_indeg[NN];
__device__ __align__(16) float  g_onorm[NN];
__device__ __align__(16) float  g_inorm[NN];
__device__ __align__(16) int    g_rowptr[NN + 1];
__device__ __align__(16) int    g_cursor[NN];
__device__ __align__(16) int    g_srcs[NE];              // edge srcs sorted by dst
__device__ __align__(16) int    g_bsum[SCAN_NB];
__device__ __align__(16) int    g_boff[SCAN_NB];
__device__ __align__(16) float  g_W1p[FIN * FHID];       // W1 tf32, MMA-fragment-permuted
__device__ __align__(16) float  g_W2p[FHID * FOUT];      // W2 tf32, MMA-fragment-permuted
__device__ __align__(16) __half g_h1[(size_t)NN * FHID]; // x @ W1 (NO norm), fp16
__device__ __align__(16) __half g_h2[(size_t)NN * FOUT]; // x2 @ W2, fp16

#define CP_COMMIT() asm volatile("cp.async.commit_group;\n" ::: "memory")
#define CP_WAIT(n)  asm volatile("cp.async.wait_group %0;\n" :: "n"(n) : "memory")

__device__ __forceinline__ void cp_async16(void* smem, const void* g, bool pred) {
    unsigned saddr = (unsigned)__cvta_generic_to_shared(smem);
    int sz = pred ? 16 : 0;   // src-size 0 -> zero-fill, no read
    asm volatile("cp.async.cg.shared.global [%0], [%1], 16, %2;\n"
                 :: "r"(saddr), "l"(g), "r"(sz));
}

__device__ __forceinline__ unsigned f2tf32(float x) {
    unsigned r;
    asm("cvt.rna.tf32.f32 %0, %1;" : "=r"(r) : "f"(x));
    return r;
}

__device__ __forceinline__ void mma_tf32(float* c, const unsigned* a, const unsigned* b) {
    asm volatile(
        "mma.sync.aligned.m16n8k8.row.col.f32.tf32.tf32.f32 "
        "{%0,%1,%2,%3}, {%4,%5,%6,%7}, {%8,%9}, {%0,%1,%2,%3};"
        : "+f"(c[0]), "+f"(c[1]), "+f"(c[2]), "+f"(c[3])
        : "r"(a[0]), "r"(a[1]), "r"(a[2]), "r"(a[3]), "r"(b[0]), "r"(b[1]));
}

// accumulate 8 halves (uint4) scaled by s into a[0..7]
__device__ __forceinline__ void acc8(float* a, uint4 u, float s) {
    float2 f;
    f = __half22float2(*(__half2*)&u.x); a[0] = fmaf(f.x, s, a[0]); a[1] = fmaf(f.y, s, a[1]);
    f = __half22float2(*(__half2*)&u.y); a[2] = fmaf(f.x, s, a[2]); a[3] = fmaf(f.y, s, a[3]);
    f = __half22float2(*(__half2*)&u.z); a[4] = fmaf(f.x, s, a[4]); a[5] = fmaf(f.y, s, a[5]);
    f = __half22float2(*(__half2*)&u.w); a[6] = fmaf(f.x, s, a[6]); a[7] = fmaf(f.y, s, a[7]);
}

// ---------------- CSR build chain (side stream) -----------------------------
__global__ void hist_kernel(const int* __restrict__ src, const int* __restrict__ dst) {
    int base = blockIdx.x * blockDim.x * 4 + threadIdx.x;
#pragma unroll
    for (int k = 0; k < 4; k++) {
        int i = base + k * blockDim.x;
        if (i < NE) {
            atomicAdd(&g_outdeg[src[i]], 1);
            atomicAdd(&g_indeg[dst[i]], 1);
        }
    }
}

__global__ void scan_blocks_kernel() {
    __shared__ int sh[SCAN_BLK];
    int t = threadIdx.x;
    int idx = blockIdx.x * SCAN_BLK + t;
    int v = (idx < NN) ? g_indeg[idx] : 0;
    sh[t] = v;
    __syncthreads();
    for (int off = SCAN_BLK >> 1; off > 0; off >>= 1) {
        if (t < off) sh[t] += sh[t + off];
        __syncthreads();
    }
    if (t == 0) g_bsum[blockIdx.x] = sh[0];
}

__global__ void scan_tops_kernel() {
    __shared__ int sh[128];
    int t = threadIdx.x;
    int v = (t < SCAN_NB) ? g_bsum[t] : 0;
    sh[t] = v;
    __syncthreads();
    for (int off = 1; off < 128; off <<= 1) {
        int a = (t >= off) ? sh[t - off] : 0;
        __syncthreads();
        sh[t] += a;
        __syncthreads();
    }
    if (t < SCAN_NB) g_boff[t] = sh[t] - v;
}

__global__ void scan_final_kernel() {
    __shared__ int sh[SCAN_BLK];
    int t = threadIdx.x;
    int idx = blockIdx.x * SCAN_BLK + t;
    int v = (idx < NN) ? g_indeg[idx] : 0;
    sh[t] = v;
    __syncthreads();
    for (int off = 1; off < SCAN_BLK; off <<= 1) {
        int a = (t >= off) ? sh[t - off] : 0;
        __syncthreads();
        sh[t] += a;
        __syncthreads();
    }
    if (idx < NN) {
        int p = g_boff[blockIdx.x] + sh[t] - v;   // exclusive
        g_rowptr[idx] = p;
        g_cursor[idx] = p;
        g_onorm[idx] = rsqrtf(fmaxf((float)g_outdeg[idx], 1.0f));
        g_inorm[idx] = rsqrtf(fmaxf((float)v, 1.0f));
        if (idx == NN - 1) g_rowptr[NN] = NE;
    }
}

__global__ void place_kernel(const int* __restrict__ src, const int* __restrict__ dst) {
    int base = blockIdx.x * blockDim.x * 8 + threadIdx.x;
#pragma unroll
    for (int k = 0; k < 8; k++) {
        int i = base + k * blockDim.x;
        if (i < NE) {
            int p = atomicAdd(&g_cursor[dst[i]], 1);
            g_srcs[p] = src[i];
        }
    }
}

// ---------------- weight prep: tf32 round + fragment permutation ------------
__global__ void cvtW_kernel(const float* __restrict__ W1, const float* __restrict__ W2) {
    int i = blockIdx.x * blockDim.x + threadIdx.x;
    if (i < FIN * FHID) {
        int p = i >> 1, f = i & 1;
        int l = p & 31, cb = (p >> 5) & 15, ks = (p >> 9) & 3, it = p >> 11;
        int srow = it * 32 + ks * 8 + f * 4 + (l & 3);
        int scol = cb * 8 + (l >> 2);
        g_W1p[i] = __uint_as_float(f2tf32(W1[srow * FHID + scol]));
    } else if (i < FIN * FHID + FHID * FOUT) {
        int j = i - FIN * FHID;
        int p = j >> 1, f = j & 1;
        int l = p & 31, cb = (p >> 5) & 7, ksg = p >> 8;
        int srow = ksg * 8 + f * 4 + (l & 3);
        int scol = cb * 8 + (l >> 2);
        g_W2p[j] = __uint_as_float(f2tf32(W2[srow * FOUT + scol]));
    }
}

// ---------------- GEMM1: persistent, tf32 MMA, 3-stage cp.async -------------
// R12 configuration verbatim (best measured: 51.1us). BM=128, BN=128, BK=32,
// grid=148 (1 block/SM), 256 threads, 8 warps (4x2), warp tile 32x64.
#define AS_STRIDE 36   // words; A-frag reads hit 32 distinct banks, 16B rows
#define BSTAGE    (32 * 128)   // 4096 words, dense permuted
__global__ __launch_bounds__(256, 1) void gemm1_kernel(const float* __restrict__ A) {
    __shared__ float As[3][128 * AS_STRIDE];
    __shared__ float Bs[3][BSTAGE];
    const int tid  = threadIdx.x;
    const int wid  = tid >> 5;
    const int lane = tid & 31;
    const int warp_m = wid >> 1;
    const int warp_n = wid & 1;
    const int lq = lane >> 2;
    const int lr = lane & 3;

    const int my_nt = (NTILES - 1 - blockIdx.x) / GRID1 + 1;
    const int J = my_nt * 16;   // flat (tile, k-iter) iterations

    float acc[2][8][4];

    auto load_stage = [&](int buf, int j) {
        const int row0 = (blockIdx.x + (j >> 4) * GRID1) * 128;
        const int k0 = (j & 15) * 32;
#pragma unroll
        for (int l = tid; l < 128 * 8; l += 256) {      // A: 128x32
            int r = l >> 3, c4 = l & 7;
            int grow = row0 + r;
            bool ok = grow < NN;
            const float* gp = A + (size_t)(ok ? grow : 0) * FIN + k0 + (c4 << 2);
            cp_async16(&As[buf][r * AS_STRIDE + (c4 << 2)], gp, ok);
        }
        const float* bg = g_W1p + (size_t)(j & 15) * BSTAGE;
#pragma unroll
        for (int l = tid; l < BSTAGE / 4; l += 256) {   // B: dense 16KB
            cp_async16(&Bs[buf][l << 2], bg + (l << 2), true);
        }
    };

    load_stage(0, 0); CP_COMMIT();
    load_stage(1, 1); CP_COMMIT();

    for (int j = 0; j < J; ++j) {
        if (j + 1 < J) CP_WAIT(1); else CP_WAIT(0);
        __syncthreads();   // stage j visible; all warps done with stage j-1
        if ((j & 15) == 0) {
#pragma unroll
            for (int mt = 0; mt < 2; mt++)
#pragma unroll
                for (int nt = 0; nt < 8; nt++)
#pragma unroll
                    for (int q = 0; q < 4; q++) acc[mt][nt][q] = 0.f;
        }
        const int buf = j % 3;
        const float* as = As[buf];
        const float* bs = Bs[buf];
#pragma unroll
        for (int ks = 0; ks < 4; ks++) {
            const int kk = ks << 3;
            unsigned af[2][4];
#pragma unroll
            for (int mt = 0; mt < 2; mt++) {
                int row = warp_m * 32 + mt * 16 + lq;
                af[mt][0] = f2tf32(as[row * AS_STRIDE + kk + lr]);
                af[mt][1] = f2tf32(as[(row + 8) * AS_STRIDE + kk + lr]);
                af[mt][2] = f2tf32(as[row * AS_STRIDE + kk + 4 + lr]);
                af[mt][3] = f2tf32(as[(row + 8) * AS_STRIDE + kk + 4 + lr]);
            }
            unsigned bf[8][2];
#pragma unroll
            for (int nt = 0; nt < 8; nt++) {
                int cb = warp_n * 8 + nt;
                const float2 bp = *(const float2*)&bs[((ks * 16 + cb) * 32 + lane) * 2];
                bf[nt][0] = __float_as_uint(bp.x);
                bf[nt][1] = __float_as_uint(bp.y);
            }
#pragma unroll
            for (int mt = 0; mt < 2; mt++)
#pragma unroll
                for (int nt = 0; nt < 8; nt++)
                    mma_tf32(acc[mt][nt], af[mt], bf[nt]);
        }
        if (j + 2 < J) {   // prefetch distance 2; buffer consumed at j-1
            load_stage((j + 2) % 3, j + 2);
            CP_COMMIT();
        }
        if ((j & 15) == 15) {   // tile epilogue: regs -> gmem
            const int row0 = (blockIdx.x + (j >> 4) * GRID1) * 128;
#pragma unroll
            for (int mt = 0; mt < 2; mt++) {
                int rowA = row0 + warp_m * 32 + mt * 16 + lq;
                int rowB = rowA + 8;
#pragma unroll
                for (int nt = 0; nt < 8; nt++) {
                    int col = warp_n * 64 + nt * 8 + (lr << 1);
                    if (rowA < NN)
                        *(__half2*)(g_h1 + (size_t)rowA * FHID + col) =
                            __float22half2_rn(make_float2(acc[mt][nt][0], acc[mt][nt][1]));
                    if (rowB < NN)
                        *(__half2*)(g_h1 + (size_t)rowB * FHID + col) =
                            __float22half2_rn(make_float2(acc[mt][nt][2], acc[mt][nt][3]));
                }
            }
        }
    }
}

// ---------------- layer2: fused agg1 + epilogue1 + GEMM2 (tf32 MMA) --------
// BM=64. x2 tile stored fp16 (smem ~49.5KB -> 3 blocks/SM, was 2 at 67KB).
// Gather: 16 half-warps work-steal rows, 4 edges in flight per half-warp.
__global__ __launch_bounds__(256, 3) void layer2_kernel(const float* __restrict__ b1) {
    __shared__ float  Ws[FHID * FOUT];   // 32KB, dense permuted W2p
    __shared__ __half x2s[64][136];      // fp16 tile, stride 272B (16B aligned)
    __shared__ int nextrow;
    const int tid  = threadIdx.x;
    const int wid  = tid >> 5;
    const int lane = tid & 31;
    const int r0 = blockIdx.x * 64;

    if (tid == 0) nextrow = 16;
#pragma unroll
    for (int l = tid; l < FHID * FOUT / 4; l += 256)
        *(float4*)&Ws[l << 2] = *(const float4*)&g_W2p[l << 2];
    __syncthreads();   // nextrow + Ws visible

    // Gather + epilogue1: half-warp h starts on row h, then steals rows 16..63.
    {
        const int sub = lane >> 4;     // 0,1
        const int q   = lane & 15;     // 0..15 -> halves [q*8, q*8+8)
        const unsigned hmask = 0xFFFFu << (sub * 16);
        float4 bb0 = *(const float4*)(b1 + q * 8);
        float4 bb1 = *(const float4*)(b1 + q * 8 + 4);
        int row = wid * 2 + sub;       // static first row: 0..15
        while (row < 64) {
            int grow = r0 + row;
            uint4 hout = make_uint4(0u, 0u, 0u, 0u);
            if (grow < NN) {
                float a[8] = {0.f, 0.f, 0.f, 0.f, 0.f, 0.f, 0.f, 0.f};
                int beg = g_rowptr[grow], end = g_rowptr[grow + 1];
                int e = beg;
                for (; e + 3 < end; e += 4) {   // 4 rows in flight
                    int s0 = g_srcs[e],     s1 = g_srcs[e + 1];
                    int s2 = g_srcs[e + 2], s3 = g_srcs[e + 3];
                    uint4 u0 = *(const uint4*)(g_h1 + (size_t)s0 * FHID + q * 8);
                    uint4 u1 = *(const uint4*)(g_h1 + (size_t)s1 * FHID + q * 8);
                    uint4 u2 = *(const uint4*)(g_h1 + (size_t)s2 * FHID + q * 8);
                    uint4 u3 = *(const uint4*)(g_h1 + (size_t)s3 * FHID + q * 8);
                    float os0 = g_onorm[s0], os1 = g_onorm[s1];
                    float os2 = g_onorm[s2], os3 = g_onorm[s3];
                    acc8(a, u0, os0); acc8(a, u1, os1);
                    acc8(a, u2, os2); acc8(a, u3, os3);
                }
                for (; e + 1 < end; e += 2) {
                    int s0 = g_srcs[e], s1 = g_srcs[e + 1];
                    uint4 u0 = *(const uint4*)(g_h1 + (size_t)s0 * FHID + q * 8);
                    uint4 u1 = *(const uint4*)(g_h1 + (size_t)s1 * FHID + q * 8);
                    float os0 = g_onorm[s0], os1 = g_onorm[s1];
                    acc8(a, u0, os0); acc8(a, u1, os1);
                }
                if (e < end) {
                    int s0 = g_srcs[e];
                    uint4 u0 = *(const uint4*)(g_h1 + (size_t)s0 * FHID + q * 8);
                    acc8(a, u0, g_onorm[s0]);
                }
                float inn = g_inorm[grow], onn = g_onorm[grow];
                float o[8];
                o[0] = fmaxf(fmaf(a[0], inn, bb0.x), 0.f) * onn;
                o[1] = fmaxf(fmaf(a[1], inn, bb0.y), 0.f) * onn;
                o[2] = fmaxf(fmaf(a[2], inn, bb0.z), 0.f) * onn;
                o[3] = fmaxf(fmaf(a[3], inn, bb0.w), 0.f) * onn;
                o[4] = fmaxf(fmaf(a[4], inn, bb1.x), 0.f) * onn;
                o[5] = fmaxf(fmaf(a[5], inn, bb1.y), 0.f) * onn;
                o[6] = fmaxf(fmaf(a[6], inn, bb1.z), 0.f) * onn;
                o[7] = fmaxf(fmaf(a[7], inn, bb1.w), 0.f) * onn;
                *(__half2*)&hout.x = __float22half2_rn(make_float2(o[0], o[1]));
                *(__half2*)&hout.y = __float22half2_rn(make_float2(o[2], o[3]));
                *(__half2*)&hout.z = __float22half2_rn(make_float2(o[4], o[5]));
                *(__half2*)&hout.w = __float22half2_rn(make_float2(o[6], o[7]));
            }
            *(uint4*)&x2s[row][q * 8] = hout;   // 16B, conflict-free
            // steal next row
            int nr = 0;
            if (q == 0) nr = atomicAdd(&nextrow, 1);
            nr = __shfl_sync(hmask, nr, sub * 16);
            row = nr;
        }
    }
    __syncthreads();

    // MMA phase: warp_m = wid>>1 (0..3) x 16 rows; warp_n = wid&1 (0..1) x 32 cols.
    const int lq = lane >> 2;
    const int lr = lane & 3;
    const int warp_m = wid >> 1;
    const int warp_n = wid & 1;
    float acc[4][4];
#pragma unroll
    for (int nt = 0; nt < 4; nt++)
#pragma unroll
        for (int qq = 0; qq < 4; qq++) acc[nt][qq] = 0.f;
    const int arow = warp_m * 16 + lq;
#pragma unroll
    for (int ks = 0; ks < 16; ks++) {
        const int kk = ks << 3;
        unsigned af[4];
        af[0] = f2tf32(__half2float(x2s[arow][kk + lr]));
        af[1] = f2tf32(__half2float(x2s[arow + 8][kk + lr]));
        af[2] = f2tf32(__half2float(x2s[arow][kk + 4 + lr]));
        af[3] = f2tf32(__half2float(x2s[arow + 8][kk + 4 + lr]));
        unsigned bf[4][2];
#pragma unroll
        for (int nt = 0; nt < 4; nt++) {
            int cb = warp_n * 4 + nt;
            const float2 bp = *(const float2*)&Ws[((ks * 8 + cb) * 32 + lane) * 2];
            bf[nt][0] = __float_as_uint(bp.x);
            bf[nt][1] = __float_as_uint(bp.y);
        }
#pragma unroll
        for (int nt = 0; nt < 4; nt++)
            mma_tf32(acc[nt], af, bf[nt]);
    }
    int rowA = r0 + warp_m * 16 + lq;
    int rowB = rowA + 8;
#pragma unroll
    for (int nt = 0; nt < 4; nt++) {
        int col = warp_n * 32 + nt * 8 + (lr << 1);
        if (rowA < NN)
            *(__half2*)(g_h2 + (size_t)rowA * FOUT + col) =
                __float22half2_rn(make_float2(acc[nt][0], acc[nt][1]));
        if (rowB < NN)
            *(__half2*)(g_h2 + (size_t)rowB * FOUT + col) =
                __float22half2_rn(make_float2(acc[nt][2], acc[nt][3]));
    }
}

// ---------------- agg2: 4 dst per warp, 4-edge MLP; re-zeroes degrees ------
// out = segsum(h2[src]) * inorm + b2.  No block barrier -> static schedule OK.
__global__ void agg2_kernel(const float* __restrict__ b2, float* __restrict__ out) {
    {
        int z = blockIdx.x * 32 + threadIdx.x;
        if (threadIdx.x < 32 && z < NN) { g_outdeg[z] = 0; g_indeg[z] = 0; }
    }
    int gw = (int)(((long long)blockIdx.x * blockDim.x + threadIdx.x) >> 5);
    int lane = threadIdx.x & 31;
    int sub = lane >> 3;           // 0..3
    int q = lane & 7;              // halves [q*8, q*8+8)
    int d = gw * 4 + sub;
    if (d >= NN) return;
    int beg = g_rowptr[d], end = g_rowptr[d + 1];
    float a[8] = {0.f, 0.f, 0.f, 0.f, 0.f, 0.f, 0.f, 0.f};
    int e = beg;
    for (; e + 3 < end; e += 4) {
        int s0 = g_srcs[e],     s1 = g_srcs[e + 1];
        int s2 = g_srcs[e + 2], s3 = g_srcs[e + 3];
        uint4 u0 = *(const uint4*)(g_h2 + (size_t)s0 * FOUT + q * 8);
        uint4 u1 = *(const uint4*)(g_h2 + (size_t)s1 * FOUT + q * 8);
        uint4 u2 = *(const uint4*)(g_h2 + (size_t)s2 * FOUT + q * 8);
        uint4 u3 = *(const uint4*)(g_h2 + (size_t)s3 * FOUT + q * 8);
        acc8(a, u0, 1.0f); acc8(a, u1, 1.0f);
        acc8(a, u2, 1.0f); acc8(a, u3, 1.0f);
    }
    for (; e + 1 < end; e += 2) {
        int s0 = g_srcs[e], s1 = g_srcs[e + 1];
        uint4 u0 = *(const uint4*)(g_h2 + (size_t)s0 * FOUT + q * 8);
        uint4 u1 = *(const uint4*)(g_h2 + (size_t)s1 * FOUT + q * 8);
        acc8(a, u0, 1.0f); acc8(a, u1, 1.0f);
    }
    if (e < end) {
        int s0 = g_srcs[e];
        uint4 u0 = *(const uint4*)(g_h2 + (size_t)s0 * FOUT + q * 8);
        acc8(a, u0, 1.0f);
    }
    float inn = g_inorm[d];
    float4 bb0 = *(const float4*)(b2 + q * 8);
    float4 bb1 = *(const float4*)(b2 + q * 8 + 4);
    float4 r0, r1;
    r0.x = fmaf(a[0], inn, bb0.x); r0.y = fmaf(a[1], inn, bb0.y);
    r0.z = fmaf(a[2], inn, bb0.z); r0.w = fmaf(a[3], inn, bb0.w);
    r1.x = fmaf(a[4], inn, bb1.x); r1.y = fmaf(a[5], inn, bb1.y);
    r1.z = fmaf(a[6], inn, bb1.z); r1.w = fmaf(a[7], inn, bb1.w);
    *(float4*)(out + (size_t)d * FOUT + q * 8)     = r0;
    *(float4*)(out + (size_t)d * FOUT + q * 8 + 4) = r1;
}

// ---------------- launch: fork CSR chain onto side stream (R12 layout) -----
extern "C" void kernel_launch(void* const* d_in, const int* in_sizes, int n_in,
                              void* d_out, int out_size) {
    const float* features = (const float*)d_in[0];
    const int*   esrc     = (const int*)d_in[1];
    const int*   edst     = (const int*)d_in[2];
    const float* W1       = (const float*)d_in[3];
    const float* b1       = (const float*)d_in[4];
    const float* W2       = (const float*)d_in[5];
    const float* b2       = (const float*)d_in[6];
    float* out = (float*)d_out;

    static cudaStream_t s1 = nullptr;
    static cudaEvent_t evFork = nullptr, evJoin = nullptr;
    if (s1 == nullptr) {
        cudaStreamCreateWithFlags(&s1, cudaStreamNonBlocking);
        cudaEventCreateWithFlags(&evFork, cudaEventDisableTiming);
        cudaEventCreateWithFlags(&evJoin, cudaEventDisableTiming);
    }

    cudaEventRecord(evFork, 0);
    cudaStreamWaitEvent(s1, evFork, 0);

    cvtW_kernel<<<(FIN * FHID + FHID * FOUT + 255) / 256, 256>>>(W1, W2);  // #1 (main)
    hist_kernel<<<(NE + 1023) / 1024, 256, 0, s1>>>(esrc, edst);           // #2 (s1)
    scan_blocks_kernel<<<SCAN_NB, SCAN_BLK, 0, s1>>>();                    // #3 (s1)
    gemm1_kernel<<<GRID1, 256>>>(features);                                // #4 (main) <- profiled
    scan_tops_kernel<<<1, 128, 0, s1>>>();                                 // #5 (s1)
    scan_final_kernel<<<SCAN_NB, SCAN_BLK, 0, s1>>>();                     // #6 (s1)
    place_kernel<<<(NE + 2047) / 2048, 256, 0, s1>>>(esrc, edst);          // #7 (s1)
    cudaEventRecord(evJoin, s1);

    cudaStreamWaitEvent(0, evJoin, 0);
    layer2_kernel<<<(NN + 63) / 64, 256>>>(b1);                            // #8
    agg2_kernel<<<(NN + 31) / 32, 256>>>(b2, out);                         // #9
}